// round 16
// baseline (speedup 1.0000x reference)
#include <cuda_runtime.h>
#include <cuda_fp16.h>

#define NPIX 16384   // 128*128 ROI pixels
#define NS   64      // sensors
#define NT   2030    // time samples
#define NB   64      // batch
#define SNT  (NS*NT) // 129920

// Transposed fp16 sinogram: [s][t][b]  (16.6 MB -> L2-resident)
__device__ __half g_t16[NS * NT * NB];
__device__ float  g_bmax[NB];

// Transpose+quantize: sino [b][s*t] fp32 -> g_t16 [s*t][b] fp16.
// 2 tiles of [64 b][64 st] per block. Also zero-inits g_bmax.
__global__ __launch_bounds__(512) void transpose_kernel(
    const float* __restrict__ sino)
{
    __shared__ float tile[64 * 64];
    const int tid = threadIdx.x;
    const int l   = tid & 31;
    const int w   = tid >> 5;

    if (blockIdx.x == 0 && tid < NB) g_bmax[tid] = 0.0f;

    unsigned int* __restrict__ dst = reinterpret_cast<unsigned int*>(g_t16);

    #pragma unroll
    for (int tt = 0; tt < 2; ++tt) {
        const int st0 = (blockIdx.x * 2 + tt) * 64;

        #pragma unroll
        for (int k = 0; k < 4; ++k) {
            const int r  = w * 4 + k;
            const int sw = (r >> 1) & 31;
            float2 v = *reinterpret_cast<const float2*>(
                sino + (size_t)r * SNT + st0 + 2 * l);
            tile[r * 64 + ((2 * l)     ^ sw)] = v.x;
            tile[r * 64 + ((2 * l + 1) ^ sw)] = v.y;
        }
        __syncthreads();

        #pragma unroll
        for (int k = 0; k < 4; ++k) {
            const int st = w * 4 + k;
            const int cs = st ^ l;
            __half2 h = __floats2half2_rn(tile[(2 * l) * 64 + cs],
                                          tile[(2 * l + 1) * 64 + cs]);
            dst[(size_t)(st0 + st) * 32 + l] =
                *reinterpret_cast<unsigned int*>(&h);
        }
        __syncthreads();
    }
}

// Block = 1024 thr = 32 warps, 64-pixel tile (two 32-px groups).
// Sensors processed in PAIRS: one __syncthreads per 2 sensors; gathers
// prefetched a full pair ahead. Gather: warp = pixel pair {w,w+32},
// lane = batch-pair (dense 128B fp16 lines). Store: warp = batches
// {2w,2w+1}, 256B contiguous spans.
__global__ __launch_bounds__(1024) void das_kernel(
    const float* __restrict__ wts,    // [NPIX][NS]
    const int*   __restrict__ tidx,   // [NPIX][NS]
    float*       __restrict__ out)    // [NB*NPIX das | NB*NS*NPIX pixel_interp]
{
    __shared__ int   sm_off[64][64];            // (s*NT+t)*32 half2-row offs
    __shared__ float sm_w  [64][64];
    __shared__ float ex[2][2][2][2][32][33];    // [buf][slice][grp][plane][w][l]

    const int tid = threadIdx.x;
    const int l   = tid & 31;
    const int w   = tid >> 5;
    const int px0 = blockIdx.x * 64;

    // ---- preload geometry: 64 pixels x 64 sensors (coalesced) ----
    #pragma unroll
    for (int k = 0; k < 4; ++k) {
        const int e  = tid + k * 1024;
        const int pp = e >> 6;
        const int s  = e & 63;
        int   t = tidx[(px0 + pp) * NS + s];
        float v = wts [(px0 + pp) * NS + s];
        v = (t >= 0 && t < NT) ? v : 0.0f;
        t = min(max(t, 0), NT - 1);
        sm_off[pp][s] = (s * NT + t) * 32;
        sm_w  [pp][s] = v;
    }
    __syncthreads();

    const unsigned int* __restrict__ g2 =
        reinterpret_cast<const unsigned int*>(g_t16);
    float* __restrict__ pi = out + NB * NPIX;

    float2 acc0 = make_float2(0.0f, 0.0f);   // pixel w
    float2 acc1 = make_float2(0.0f, 0.0f);   // pixel w+32

    // prologue: gather sensor pair {0,1}; h[slice][group]
    unsigned int h[2][2]; float cw[2][2];
    #pragma unroll
    for (int e = 0; e < 2; ++e) {
        h[e][0]  = __ldg(g2 + sm_off[w][e]      + l);
        h[e][1]  = __ldg(g2 + sm_off[w + 32][e] + l);
        cw[e][0] = sm_w[w][e];
        cw[e][1] = sm_w[w + 32][e];
    }

    for (int u = 0; u < NS / 2; ++u) {
        const int s0 = 2 * u;

        // prefetch next sensor pair (overlaps exchange + stores)
        unsigned int hn[2][2]; float wn[2][2];
        if (u + 1 < NS / 2) {
            #pragma unroll
            for (int e = 0; e < 2; ++e) {
                const int sn = s0 + 2 + e;
                hn[e][0] = __ldg(g2 + sm_off[w][sn]      + l);
                hn[e][1] = __ldg(g2 + sm_off[w + 32][sn] + l);
                wn[e][0] = sm_w[w][sn];
                wn[e][1] = sm_w[w + 32][sn];
            }
        }

        const int p = u & 1;
        #pragma unroll
        for (int e = 0; e < 2; ++e) {
            float2 v0 = __half22float2(*reinterpret_cast<__half2*>(&h[e][0]));
            float2 v1 = __half22float2(*reinterpret_cast<__half2*>(&h[e][1]));
            v0.x *= cw[e][0]; v0.y *= cw[e][0];
            v1.x *= cw[e][1]; v1.y *= cw[e][1];
            acc0.x += v0.x; acc0.y += v0.y;
            acc1.x += v1.x; acc1.y += v1.y;
            ex[p][e][0][0][w][l] = v0.x;
            ex[p][e][0][1][w][l] = v0.y;
            ex[p][e][1][0][w][l] = v1.x;
            ex[p][e][1][1][w][l] = v1.y;
        }
        __syncthreads();              // ONE barrier per 2 sensors

        // store role: batches 2w,2w+1; 256B spans; both sensors of the pair
        #pragma unroll
        for (int e = 0; e < 2; ++e) {
            #pragma unroll
            for (int hb = 0; hb < 2; ++hb) {
                const int bb = 2 * w + hb;
                const size_t o = ((size_t)bb * NS + s0 + e) * NPIX + px0 + l;
                __stcs(pi + o,      ex[p][e][0][hb][l][w]);
                __stcs(pi + o + 32, ex[p][e][1][hb][l][w]);
            }
        }

        #pragma unroll
        for (int e = 0; e < 2; ++e) {
            h[e][0] = hn[e][0]; h[e][1] = hn[e][1];
            cw[e][0] = wn[e][0]; cw[e][1] = wn[e][1];
        }
    }

    // ---- das epilogue: exchange acc, relu, store (write-back -> L2 for
    //      norm), per-batch max ----
    __syncthreads();
    ex[0][0][0][0][w][l] = acc0.x;
    ex[0][0][0][1][w][l] = acc0.y;
    ex[0][0][1][0][w][l] = acc1.x;
    ex[0][0][1][1][w][l] = acc1.y;
    __syncthreads();
    #pragma unroll
    for (int hb = 0; hb < 2; ++hb) {
        const int bb = 2 * w + hb;
        float d0 = fmaxf(ex[0][0][0][hb][l][w], 0.0f);
        float d1 = fmaxf(ex[0][0][1][hb][l][w], 0.0f);
        out[(size_t)bb * NPIX + px0 + l]      = d0;
        out[(size_t)bb * NPIX + px0 + 32 + l] = d1;
        float m = fmaxf(d0, d1);
        #pragma unroll
        for (int off = 16; off > 0; off >>= 1)
            m = fmaxf(m, __shfl_xor_sync(0xffffffffu, m, off));
        if (l == 0)
            atomicMax(reinterpret_cast<int*>(&g_bmax[bb]), __float_as_int(m));
    }
}

__global__ __launch_bounds__(256) void norm_kernel(float* __restrict__ out)
{
    // 512 blocks x 256 thr, 2 float4 per thread
    float4* p = reinterpret_cast<float4*>(out);
    #pragma unroll
    for (int k = 0; k < 2; ++k) {
        int i = (blockIdx.x * 2 + k) * 256 + threadIdx.x;
        float4 v = p[i];
        int b = (i * 4) >> 14;
        float m = g_bmax[b];
        float r = (m > 1e-8f) ? (1.0f / m) : 1.0f;
        v.x *= r; v.y *= r; v.z *= r; v.w *= r;
        p[i] = v;
    }
}

extern "C" void kernel_launch(void* const* d_in, const int* in_sizes, int n_in,
                              void* d_out, int out_size)
{
    const float* sino = (const float*)d_in[0];   // [64,1,64,2030]
    const float* wts  = (const float*)d_in[1];   // [128,128,64]
    const int*   tidx = (const int*)d_in[2];     // [128,128,64]
    float* out = (float*)d_out;

    transpose_kernel<<<SNT / 128, 512>>>(sino);         // 1015 blocks

    das_kernel<<<NPIX / 64, 1024>>>(wts, tidx, out);    // 256 blocks

    norm_kernel<<<NB * NPIX / 4 / 512, 256>>>(out);     // 512 blocks
}

// round 17
// speedup vs baseline: 1.1927x; 1.1927x over previous
#include <cuda_runtime.h>
#include <cuda_fp16.h>

#define NPIX 16384   // 128*128 ROI pixels
#define NS   64      // sensors
#define NT   2030    // time samples
#define NB   64      // batch
#define SNT  (NS*NT) // 129920

// Transposed fp16 sinogram: [s][t][b]  (16.6 MB -> L2-resident)
__device__ __half g_t16[NS * NT * NB];
__device__ float  g_bmax[NB];

// Transpose+quantize: sino [b][s*t] fp32 -> g_t16 [s*t][b] fp16.
// 4 tiles of [64 b][64 st] per block. Also zero-inits g_bmax.
__global__ __launch_bounds__(512) void transpose_kernel(
    const float* __restrict__ sino)
{
    __shared__ float tile[64 * 64];
    const int tid = threadIdx.x;
    const int l   = tid & 31;
    const int w   = tid >> 5;

    if (blockIdx.x == 0 && tid < NB) g_bmax[tid] = 0.0f;

    unsigned int* __restrict__ dst = reinterpret_cast<unsigned int*>(g_t16);

    for (int tt = 0; tt < 4; ++tt) {
        const int st0 = (blockIdx.x * 4 + tt) * 64;
        if (st0 >= SNT) break;

        #pragma unroll
        for (int k = 0; k < 4; ++k) {
            const int r  = w * 4 + k;
            const int sw = (r >> 1) & 31;
            float2 v = *reinterpret_cast<const float2*>(
                sino + (size_t)r * SNT + st0 + 2 * l);
            tile[r * 64 + ((2 * l)     ^ sw)] = v.x;
            tile[r * 64 + ((2 * l + 1) ^ sw)] = v.y;
        }
        __syncthreads();

        #pragma unroll
        for (int k = 0; k < 4; ++k) {
            const int st = w * 4 + k;
            const int cs = st ^ l;
            __half2 h = __floats2half2_rn(tile[(2 * l) * 64 + cs],
                                          tile[(2 * l + 1) * 64 + cs]);
            dst[(size_t)(st0 + st) * 32 + l] =
                *reinterpret_cast<unsigned int*>(&h);
        }
        __syncthreads();
    }
}

// Block = 1024 thr = 32 warps, 64-pixel tile (two 32-px groups).
// Gather: warp = pixel pair {w, w+32}, lane = batch-pair (dense 128B lines).
// Exchange: float2 STS.64/LDS.64, conflict-free (banks (2w+2l) per phase).
// Store: warp = batches {2w, 2w+1}, 256B contiguous per (b,s) per block.
__global__ __launch_bounds__(1024) void das_kernel(
    const float* __restrict__ wts,    // [NPIX][NS]
    const int*   __restrict__ tidx,   // [NPIX][NS]
    float*       __restrict__ out)    // [NB*NPIX das | NB*NS*NPIX pixel_interp]
{
    __shared__ int    sm_off[64][64];       // (s*NT+t)*32 half2-row offsets
    __shared__ float  sm_w  [64][64];
    __shared__ float2 ex[2][2][32][33];     // [buf][group][w][l] float2

    const int tid = threadIdx.x;
    const int l   = tid & 31;
    const int w   = tid >> 5;
    const int px0 = blockIdx.x * 64;

    // ---- preload geometry: 64 pixels x 64 sensors (coalesced) ----
    #pragma unroll
    for (int k = 0; k < 4; ++k) {
        const int e  = tid + k * 1024;
        const int pp = e >> 6;
        const int s  = e & 63;
        int   t = tidx[(px0 + pp) * NS + s];
        float v = wts [(px0 + pp) * NS + s];
        v = (t >= 0 && t < NT) ? v : 0.0f;
        t = min(max(t, 0), NT - 1);
        sm_off[pp][s] = (s * NT + t) * 32;
        sm_w  [pp][s] = v;
    }
    __syncthreads();

    const unsigned int* __restrict__ g2 =
        reinterpret_cast<const unsigned int*>(g_t16);
    float* __restrict__ pi = out + NB * NPIX;
    float2 acc0 = make_float2(0.0f, 0.0f);   // pixel w
    float2 acc1 = make_float2(0.0f, 0.0f);   // pixel w+32

    // prologue: gather s=0 for both pixel groups
    unsigned int h0 = __ldg(g2 + sm_off[w][0]      + l);
    unsigned int h1 = __ldg(g2 + sm_off[w + 32][0] + l);
    float        w0 = sm_w[w][0];
    float        w1 = sm_w[w + 32][0];

    for (int s = 0; s < NS; ++s) {
        // prefetch next sensor (overlaps exchange+stores)
        unsigned int h0n = 0, h1n = 0; float w0n = 0.0f, w1n = 0.0f;
        if (s + 1 < NS) {
            h0n = __ldg(g2 + sm_off[w][s + 1]      + l);
            h1n = __ldg(g2 + sm_off[w + 32][s + 1] + l);
            w0n = sm_w[w][s + 1];
            w1n = sm_w[w + 32][s + 1];
        }

        float2 v0 = __half22float2(*reinterpret_cast<__half2*>(&h0));
        float2 v1 = __half22float2(*reinterpret_cast<__half2*>(&h1));
        v0.x *= w0; v0.y *= w0;  acc0.x += v0.x; acc0.y += v0.y;
        v1.x *= w1; v1.y *= w1;  acc1.x += v1.x; acc1.y += v1.y;

        const int p = s & 1;
        ex[p][0][w][l] = v0;          // STS.64: (batch 2l, 2l+1) of pixel w
        ex[p][1][w][l] = v1;          //                       of pixel w+32
        __syncthreads();              // single barrier (double-buffered)

        // store role: LDS.64 -> batches 2w, 2w+1; 256B spans per (b,s)
        const float2 u0 = ex[p][0][l][w];
        const float2 u1 = ex[p][1][l][w];
        {
            const size_t o = ((size_t)(2 * w) * NS + s) * NPIX + px0 + l;
            __stcs(pi + o,      u0.x);
            __stcs(pi + o + 32, u1.x);
        }
        {
            const size_t o = ((size_t)(2 * w + 1) * NS + s) * NPIX + px0 + l;
            __stcs(pi + o,      u0.y);
            __stcs(pi + o + 32, u1.y);
        }
        h0 = h0n; h1 = h1n; w0 = w0n; w1 = w1n;
    }

    // ---- das epilogue: exchange acc, relu, store (write-back: stays in L2
    //      for norm_kernel), per-batch max ----
    __syncthreads();
    ex[0][0][w][l] = acc0;
    ex[0][1][w][l] = acc1;
    __syncthreads();
    const float2 a0 = ex[0][0][l][w];
    const float2 a1 = ex[0][1][l][w];
    #pragma unroll
    for (int hb = 0; hb < 2; ++hb) {
        const int bb = 2 * w + hb;
        float d0 = fmaxf(hb ? a0.y : a0.x, 0.0f);
        float d1 = fmaxf(hb ? a1.y : a1.x, 0.0f);
        out[(size_t)bb * NPIX + px0 + l]      = d0;
        out[(size_t)bb * NPIX + px0 + 32 + l] = d1;
        float m = fmaxf(d0, d1);
        #pragma unroll
        for (int off = 16; off > 0; off >>= 1)
            m = fmaxf(m, __shfl_xor_sync(0xffffffffu, m, off));
        if (l == 0)
            atomicMax(reinterpret_cast<int*>(&g_bmax[bb]), __float_as_int(m));
    }
}

__global__ __launch_bounds__(256) void norm_kernel(float* __restrict__ out)
{
    float4* p = reinterpret_cast<float4*>(out);
    #pragma unroll
    for (int k = 0; k < 2; ++k) {
        int i = (blockIdx.x * 2 + k) * 256 + threadIdx.x;
        float4 v = p[i];
        int b = (i * 4) >> 14;
        float m = g_bmax[b];
        float r = (m > 1e-8f) ? (1.0f / m) : 1.0f;
        v.x *= r; v.y *= r; v.z *= r; v.w *= r;
        p[i] = v;
    }
}

extern "C" void kernel_launch(void* const* d_in, const int* in_sizes, int n_in,
                              void* d_out, int out_size)
{
    const float* sino = (const float*)d_in[0];   // [64,1,64,2030]
    const float* wts  = (const float*)d_in[1];   // [128,128,64]
    const int*   tidx = (const int*)d_in[2];     // [128,128,64]
    float* out = (float*)d_out;

    transpose_kernel<<<(SNT + 255) / 256, 512>>>(sino);   // 508 blocks

    das_kernel<<<NPIX / 64, 1024>>>(wts, tidx, out);      // 256 blocks

    norm_kernel<<<NB * NPIX / 4 / 512, 256>>>(out);       // 512 blocks
}